// round 10
// baseline (speedup 1.0000x reference)
#include <cuda_runtime.h>
#include <cstdint>
#include <cstddef>

// ---------------- problem constants ----------------
// inputs: (4,1024,2048) f32  -> B=4096 rows, D_IN=2048
// core_i: (8, 512*512, 8) f32, viewed as G[r][o][x][s], strides: r:2097152, o:4096, x:8, s:1
// bias: (2048,)
// out: (4096, 2048) f32
#define NB 4096
#define RDIM 8
#define NSEG 4
#define LSEG 512
#define CORE_RSTRIDE 2097152   // 512*512*8

// ---------------- scratch (device globals; no allocation allowed) ----------------
__device__ float g_xT[2048 * 4096];          // xT[d][b], 32 MB
__device__ float g_Gsum[NSEG * 8 * 4096];    // [i][r][x*8+s], 512 KB
__device__ float g_S[NSEG * NB * 64];        // [i][b][r*8+s], 4 MB
__device__ float g_env[NSEG * NB * 64];      // [i][b][r*8+s], 4 MB

// ---------------- helpers ----------------
__device__ __forceinline__ uint32_t f2tf32(float f) {
    uint32_t o;
    asm volatile("cvt.rna.tf32.f32 %0, %1;\n" : "=r"(o) : "f"(f));
    return o;
}

__device__ __forceinline__ void cpa16(void* smem_dst, const void* gsrc) {
    uint32_t s = (uint32_t)__cvta_generic_to_shared(smem_dst);
    asm volatile("cp.async.cg.shared.global [%0], [%1], 16;\n" :: "r"(s), "l"(gsrc) : "memory");
}

__device__ __forceinline__ void mma_tf32(float* c, const uint32_t* a, const uint32_t* b) {
    asm volatile(
        "mma.sync.aligned.m16n8k8.row.col.f32.tf32.tf32.f32 "
        "{%0,%1,%2,%3}, {%4,%5,%6,%7}, {%8,%9}, {%0,%1,%2,%3};\n"
        : "+f"(c[0]), "+f"(c[1]), "+f"(c[2]), "+f"(c[3])
        : "r"(a[0]), "r"(a[1]), "r"(a[2]), "r"(a[3]), "r"(b[0]), "r"(b[1]));
}

// ================= kernel 1: transpose x (4096x2048 -> 2048x4096) =================
__global__ void k_transpose(const float* __restrict__ x) {
    __shared__ float tile[32][33];
    int d0 = blockIdx.x * 32, b0 = blockIdx.y * 32;
    int tx = threadIdx.x, ty = threadIdx.y;   // 32 x 8
#pragma unroll
    for (int j = 0; j < 32; j += 8)
        tile[ty + j][tx] = x[(size_t)(b0 + ty + j) * 2048 + d0 + tx];
    __syncthreads();
#pragma unroll
    for (int j = 0; j < 32; j += 8)
        g_xT[(size_t)(d0 + ty + j) * 4096 + b0 + tx] = tile[tx][ty + j];
}

// ================= kernel 2: Gsum[i][r][x*8+s] = sum_o G_i[r,o,x,s] =================
__global__ void k_gsum(const float* __restrict__ c0, const float* __restrict__ c1,
                       const float* __restrict__ c2, const float* __restrict__ c3) {
    int i = blockIdx.y;
    const float* G = (i == 0) ? c0 : (i == 1) ? c1 : (i == 2) ? c2 : c3;
    int idx = blockIdx.x * 256 + threadIdx.x;   // 0..32767
    int r = idx >> 12, xs = idx & 4095;
    const float* p = G + (size_t)r * CORE_RSTRIDE + xs;
    float s = 0.f;
#pragma unroll 8
    for (int o = 0; o < 512; o++) s += p[(size_t)o * 4096];
    g_Gsum[(size_t)(i * 8 + r) * 4096 + xs] = s;
}

// ================= kernel 3: S[i][b][r][s] = sum_x Gsum[i][r][x][s] * x[b, i*512+x] ===
__global__ void k_S(const float* __restrict__ x) {
    __shared__ float xs_[512][17];
    int i = blockIdx.y;
    int b0 = blockIdx.x * 16;
    int t = threadIdx.x;
    for (int idx = t; idx < 16 * 512; idx += 256) {
        int b = idx >> 9, xc = idx & 511;
        xs_[xc][b] = x[(size_t)(b0 + b) * 2048 + i * 512 + xc];
    }
    __syncthreads();
    int rs = t & 63, bq = t >> 6;          // bq 0..3
    int s = rs & 7;
    int r = rs >> 3;
    const float* gp = g_Gsum + (size_t)(i * 8 + r) * 4096 + s;
    float acc[4] = {0.f, 0.f, 0.f, 0.f};
    for (int xc = 0; xc < 512; xc++) {
        float gv = gp[xc * 8];
#pragma unroll
        for (int j = 0; j < 4; j++) acc[j] += gv * xs_[xc][bq + j * 4];
    }
#pragma unroll
    for (int j = 0; j < 4; j++)
        g_S[(size_t)(i * NB + b0 + bq + j * 4) * 64 + rs] = acc[j];
}

// ================= kernel 4: ring products -> env[i][b][r][s] =================
// P0=I,P1=S0,P2=S0S1,P3=S0S1S2 ; Q0=S1S2S3,Q1=S2S3,Q2=S3,Q3=I ; env_i = (Q_i P_i)^T
__global__ void k_env() {
    int b = blockIdx.x, t = threadIdx.x;
    int r = t >> 3, c = t & 7;
    __shared__ float Sm[4][64], P2[64], P3[64], Q1[64], Q0[64], E[64];
#pragma unroll
    for (int i = 0; i < 4; i++) Sm[i][t] = g_S[(size_t)(i * NB + b) * 64 + t];
    __syncthreads();
    float v;
    v = 0.f;
#pragma unroll
    for (int k = 0; k < 8; k++) v += Sm[0][r * 8 + k] * Sm[1][k * 8 + c];
    P2[t] = v;
    v = 0.f;
#pragma unroll
    for (int k = 0; k < 8; k++) v += Sm[2][r * 8 + k] * Sm[3][k * 8 + c];
    Q1[t] = v;
    __syncthreads();
    v = 0.f;
#pragma unroll
    for (int k = 0; k < 8; k++) v += P2[r * 8 + k] * Sm[2][k * 8 + c];
    P3[t] = v;
    v = 0.f;
#pragma unroll
    for (int k = 0; k < 8; k++) v += Sm[1][r * 8 + k] * Q1[k * 8 + c];
    Q0[t] = v;
    __syncthreads();
    // env0 = Q0^T ; env3 = P3^T
    g_env[(size_t)(0 * NB + b) * 64 + t] = Q0[c * 8 + r];
    g_env[(size_t)(3 * NB + b) * 64 + t] = P3[c * 8 + r];
    // env1 = (Q1 @ S0)^T
    v = 0.f;
#pragma unroll
    for (int k = 0; k < 8; k++) v += Q1[r * 8 + k] * Sm[0][k * 8 + c];
    E[t] = v;
    __syncthreads();
    g_env[(size_t)(1 * NB + b) * 64 + t] = E[c * 8 + r];
    __syncthreads();
    // env2 = (S3 @ P2)^T
    v = 0.f;
#pragma unroll
    for (int k = 0; k < 8; k++) v += Sm[3][r * 8 + k] * P2[k * 8 + c];
    E[t] = v;
    __syncthreads();
    g_env[(size_t)(2 * NB + b) * 64 + t] = E[c * 8 + r];
}

// ================= kernel 5: main GEMM (tf32 mma) =================
// out[b, i*512+o] = sum_r sum_k A_r[b,k] * G_i[r][o,k] + bias,  k = x*8+s (K=4096 per r)
// A_r[b,k] = x[b, i*512+x] * env_i[b,r,s]  (built per-thread in registers)
#define STAGES 4
__global__ void __launch_bounds__(256, 2) k_gemm(
    const float* __restrict__ c0, const float* __restrict__ c1,
    const float* __restrict__ c2, const float* __restrict__ c3,
    const float* __restrict__ bias, float* __restrict__ out) {
    int i = blockIdx.z;
    const float* G = (i == 0) ? c0 : (i == 1) ? c1 : (i == 2) ? c2 : c3;
    int o0 = blockIdx.x * 64;
    int b0 = blockIdx.y * 128;
    int t  = threadIdx.x;
    int warp = t >> 5, lane = t & 31;
    int g = lane >> 2, tg = lane & 3;
    int wm = warp >> 1, wn = warp & 1;    // 4 x 2 warp grid
    int mW = wm * 32, nW = wn * 32;

    __shared__ float Gs[STAGES][64][36];   // stride 36 -> conflict-free frag LDS
    __shared__ float xch[STAGES][4][132];  // [x-within-chunk][b], pad 132

    const float* xTseg = g_xT + (size_t)i * 512 * 4096 + b0;

    // stage s (0..1023): r = s>>7, xc = s&127
    auto issue = [&](int s) {
        int buf = s & (STAGES - 1);
        int r = s >> 7, xc = s & 127;
        const float* Gr = G + (size_t)r * CORE_RSTRIDE + (size_t)o0 * 4096 + xc * 32;
#pragma unroll
        for (int j = 0; j < 2; j++) {
            int c = t + j * 256;
            int row = c >> 3, col = c & 7;
            cpa16(&Gs[buf][row][col * 4], Gr + (size_t)row * 4096 + col * 4);
        }
        if (t < 128) {
            int xl = t >> 5, sg = t & 31;
            cpa16(&xch[buf][xl][sg * 4], xTseg + (size_t)(xc * 4 + xl) * 4096 + sg * 4);
        }
    };

    float acc[2][4][4];
#pragma unroll
    for (int a = 0; a < 2; a++)
#pragma unroll
        for (int b = 0; b < 4; b++)
#pragma unroll
            for (int c = 0; c < 4; c++) acc[a][b][c] = 0.f;

    int b_of[4] = {mW + g, mW + g + 8, mW + g + 16, mW + g + 24};

    // prologue: stages 0..2
#pragma unroll
    for (int s = 0; s < STAGES - 1; s++) {
        issue(s);
        asm volatile("cp.async.commit_group;\n" ::: "memory");
    }

    for (int r = 0; r < 8; r++) {
        // env fragments for this r (8 scalars), from L2-hot g_env
        float et[4], et4[4];
        const float* ep = g_env + (size_t)(i * NB + b0) * 64 + r * 8;
#pragma unroll
        for (int j = 0; j < 4; j++) {
            et[j]  = ep[(size_t)b_of[j] * 64 + tg];
            et4[j] = ep[(size_t)b_of[j] * 64 + tg + 4];
        }
        for (int xc = 0; xc < 128; xc++) {
            int s = r * 128 + xc;
            int nxt = s + STAGES - 1;
            if (nxt < 1024) issue(nxt);
            asm volatile("cp.async.commit_group;\n" ::: "memory");
            asm volatile("cp.async.wait_group %0;\n" :: "n"(STAGES - 1) : "memory");
            __syncthreads();
            int buf = s & (STAGES - 1);

            float xv[4][4];
#pragma unroll
            for (int ks = 0; ks < 4; ks++)
#pragma unroll
                for (int j = 0; j < 4; j++) xv[ks][j] = xch[buf][ks][b_of[j]];

#pragma unroll
            for (int ks = 0; ks < 4; ks++) {
                uint32_t a[2][4];
#pragma unroll
                for (int mf = 0; mf < 2; mf++) {
                    a[mf][0] = f2tf32(xv[ks][mf * 2 + 0] * et[mf * 2 + 0]);
                    a[mf][1] = f2tf32(xv[ks][mf * 2 + 1] * et[mf * 2 + 1]);
                    a[mf][2] = f2tf32(xv[ks][mf * 2 + 0] * et4[mf * 2 + 0]);
                    a[mf][3] = f2tf32(xv[ks][mf * 2 + 1] * et4[mf * 2 + 1]);
                }
#pragma unroll
                for (int nf = 0; nf < 4; nf++) {
                    uint32_t bb[2];
                    bb[0] = f2tf32(Gs[buf][nW + nf * 8 + g][ks * 8 + tg]);
                    bb[1] = f2tf32(Gs[buf][nW + nf * 8 + g][ks * 8 + tg + 4]);
                    mma_tf32(acc[0][nf], a[0], bb);
                    mma_tf32(acc[1][nf], a[1], bb);
                }
            }
            __syncthreads();
        }
    }

    // epilogue
    int row0 = b0 + mW + g;
#pragma unroll
    for (int mf = 0; mf < 2; mf++) {
#pragma unroll
        for (int nf = 0; nf < 4; nf++) {
            int col = i * 512 + o0 + nW + nf * 8 + tg * 2;
            float2 bv = *(const float2*)&bias[col];
            int ra = row0 + mf * 16;
            float2 v0 = {acc[mf][nf][0] + bv.x, acc[mf][nf][1] + bv.y};
            float2 v1 = {acc[mf][nf][2] + bv.x, acc[mf][nf][3] + bv.y};
            *(float2*)&out[(size_t)ra * 2048 + col]       = v0;
            *(float2*)&out[(size_t)(ra + 8) * 2048 + col] = v1;
        }
    }
}

// ================= launch =================
extern "C" void kernel_launch(void* const* d_in, const int* in_sizes, int n_in,
                              void* d_out, int out_size) {
    (void)in_sizes; (void)n_in; (void)out_size;
    const float* x    = (const float*)d_in[0];
    const float* c0   = (const float*)d_in[1];
    const float* c1   = (const float*)d_in[2];
    const float* c2   = (const float*)d_in[3];
    const float* c3   = (const float*)d_in[4];
    const float* bias = (const float*)d_in[5];
    float* out = (float*)d_out;

    k_transpose<<<dim3(64, 128), dim3(32, 8)>>>(x);
    k_gsum<<<dim3(128, 4), 256>>>(c0, c1, c2, c3);
    k_S<<<dim3(256, 4), 256>>>(x);
    k_env<<<4096, 64>>>();
    k_gemm<<<dim3(8, 32, 4), 256>>>(c0, c1, c2, c3, bias, out);
}

// round 12
// speedup vs baseline: 1.1017x; 1.1017x over previous
#include <cuda_runtime.h>
#include <cstdint>
#include <cstddef>

// ---------------- problem constants ----------------
#define NB 4096
#define CORE_RSTRIDE 2097152   // 512*512*8 floats (r stride)
#define SEG_FLOATS   16777216  // 8 * CORE_RSTRIDE

// ---------------- scratch (device globals) ----------------
__device__ float g_xT[2048 * 4096];          // xT[d][b]  (32 MB)
__device__ float g_Gr[4 * SEG_FLOATS];       // tf32-pre-rounded G (256 MB)
__device__ float g_Gsum[4 * 8 * 4096];
__device__ float g_S[4 * NB * 64];
__device__ float g_env[4 * NB * 64];

// ---------------- helpers ----------------
__device__ __forceinline__ uint32_t f2tf32(float f) {
    uint32_t o;
    asm volatile("cvt.rna.tf32.f32 %0, %1;\n" : "=r"(o) : "f"(f));
    return o;
}
__device__ __forceinline__ void cpa16(uint32_t saddr, const void* g) {
    asm volatile("cp.async.cg.shared.global [%0], [%1], 16;\n" :: "r"(saddr), "l"(g) : "memory");
}
__device__ __forceinline__ void mma_tf32(float* c, const uint32_t* a, const uint32_t* b) {
    asm volatile(
        "mma.sync.aligned.m16n8k8.row.col.f32.tf32.tf32.f32 "
        "{%0,%1,%2,%3}, {%4,%5,%6,%7}, {%8,%9}, {%0,%1,%2,%3};\n"
        : "+f"(c[0]), "+f"(c[1]), "+f"(c[2]), "+f"(c[3])
        : "r"(a[0]), "r"(a[1]), "r"(a[2]), "r"(a[3]), "r"(b[0]), "r"(b[1]));
}

// ================= kernel 0: pre-round G to tf32 =================
__global__ void k_round(const float* __restrict__ c0, const float* __restrict__ c1,
                        const float* __restrict__ c2, const float* __restrict__ c3) {
    int seg = blockIdx.y;
    const float* G = (seg == 0) ? c0 : (seg == 1) ? c1 : (seg == 2) ? c2 : c3;
    float* D = g_Gr + (size_t)seg * SEG_FLOATS;
    size_t base = ((size_t)blockIdx.x * 256 + threadIdx.x) * 32;  // 8 float4
#pragma unroll
    for (int j = 0; j < 8; j++) {
        float4 v = *(const float4*)(G + base + j * 4);
        uint4 o;
        o.x = f2tf32(v.x); o.y = f2tf32(v.y); o.z = f2tf32(v.z); o.w = f2tf32(v.w);
        *(uint4*)(D + base + j * 4) = o;
    }
}

// ================= kernel 1: transpose x =================
__global__ void k_transpose(const float* __restrict__ x) {
    __shared__ float tile[32][33];
    int d0 = blockIdx.x * 32, b0 = blockIdx.y * 32;
    int tx = threadIdx.x, ty = threadIdx.y;
#pragma unroll
    for (int j = 0; j < 32; j += 8)
        tile[ty + j][tx] = x[(size_t)(b0 + ty + j) * 2048 + d0 + tx];
    __syncthreads();
#pragma unroll
    for (int j = 0; j < 32; j += 8)
        g_xT[(size_t)(d0 + ty + j) * 4096 + b0 + tx] = tile[tx][ty + j];
}

// ================= kernel 2: Gsum =================
__global__ void k_gsum(const float* __restrict__ c0, const float* __restrict__ c1,
                       const float* __restrict__ c2, const float* __restrict__ c3) {
    int i = blockIdx.y;
    const float* G = (i == 0) ? c0 : (i == 1) ? c1 : (i == 2) ? c2 : c3;
    int idx = blockIdx.x * 256 + threadIdx.x;
    int r = idx >> 12, xs = idx & 4095;
    const float* p = G + (size_t)r * CORE_RSTRIDE + xs;
    float s = 0.f;
#pragma unroll 8
    for (int o = 0; o < 512; o++) s += p[(size_t)o * 4096];
    g_Gsum[(size_t)(i * 8 + r) * 4096 + xs] = s;
}

// ================= kernel 3: S =================
__global__ void k_S(const float* __restrict__ x) {
    __shared__ float xs_[512][17];
    int i = blockIdx.y;
    int b0 = blockIdx.x * 16;
    int t = threadIdx.x;
    for (int idx = t; idx < 16 * 512; idx += 256) {
        int b = idx >> 9, xc = idx & 511;
        xs_[xc][b] = x[(size_t)(b0 + b) * 2048 + i * 512 + xc];
    }
    __syncthreads();
    int rs = t & 63, bq = t >> 6;
    int s = rs & 7, r = rs >> 3;
    const float* gp = g_Gsum + (size_t)(i * 8 + r) * 4096 + s;
    float acc[4] = {0.f, 0.f, 0.f, 0.f};
    for (int xc = 0; xc < 512; xc++) {
        float gv = gp[xc * 8];
#pragma unroll
        for (int j = 0; j < 4; j++) acc[j] += gv * xs_[xc][bq + j * 4];
    }
#pragma unroll
    for (int j = 0; j < 4; j++)
        g_S[(size_t)(i * NB + b0 + bq + j * 4) * 64 + rs] = acc[j];
}

// ================= kernel 4: ring products -> env =================
__global__ void k_env() {
    int b = blockIdx.x, t = threadIdx.x;
    int r = t >> 3, c = t & 7;
    __shared__ float Sm[4][64], P2[64], P3[64], Q1[64], Q0[64], E[64];
#pragma unroll
    for (int i = 0; i < 4; i++) Sm[i][t] = g_S[(size_t)(i * NB + b) * 64 + t];
    __syncthreads();
    float v;
    v = 0.f;
#pragma unroll
    for (int k = 0; k < 8; k++) v += Sm[0][r * 8 + k] * Sm[1][k * 8 + c];
    P2[t] = v;
    v = 0.f;
#pragma unroll
    for (int k = 0; k < 8; k++) v += Sm[2][r * 8 + k] * Sm[3][k * 8 + c];
    Q1[t] = v;
    __syncthreads();
    v = 0.f;
#pragma unroll
    for (int k = 0; k < 8; k++) v += P2[r * 8 + k] * Sm[2][k * 8 + c];
    P3[t] = v;
    v = 0.f;
#pragma unroll
    for (int k = 0; k < 8; k++) v += Sm[1][r * 8 + k] * Q1[k * 8 + c];
    Q0[t] = v;
    __syncthreads();
    g_env[(size_t)(0 * NB + b) * 64 + t] = Q0[c * 8 + r];
    g_env[(size_t)(3 * NB + b) * 64 + t] = P3[c * 8 + r];
    v = 0.f;
#pragma unroll
    for (int k = 0; k < 8; k++) v += Q1[r * 8 + k] * Sm[0][k * 8 + c];
    E[t] = v;
    __syncthreads();
    g_env[(size_t)(1 * NB + b) * 64 + t] = E[c * 8 + r];
    __syncthreads();
    v = 0.f;
#pragma unroll
    for (int k = 0; k < 8; k++) v += Sm[3][r * 8 + k] * P2[k * 8 + c];
    E[t] = v;
    __syncthreads();
    g_env[(size_t)(2 * NB + b) * 64 + t] = E[c * 8 + r];
}

// ================= kernel 5: main GEMM (tf32 mma, 64x64 warp tile) =================
// CTA 128(M=b) x 128(N=o), 128 threads (2x2 warps, warp tile 64x64).
// out[b, seg*512+o] = sum_r sum_k A_r[b,k]*G[r][o,k] + bias, k=x*8+s, K=4096/r.
// A_r[b,k] = x[b, seg*512+x] * env[seg][b][r][s], built in registers (pre-rounded tf32).
// B (G) pre-rounded to tf32 in g_Gr -> raw LDS bits feed mma (no cvt).
#define STAGES 4
// smem byte layout (dynamic):
//   Bs:  [STAGES][128][36] f32  -> stage stride 18432, row stride 144
//   xch: [STAGES][4][132] f32   -> base 73728, stage stride 2112, row stride 528
#define BS_STAGE   18432
#define BS_ROW     144
#define XCH_BASE   73728
#define XCH_STAGE  2112
#define XCH_ROW    528
#define GEMM_SMEM  (XCH_BASE + STAGES * XCH_STAGE)

__global__ void __launch_bounds__(128, 2) k_gemm(
    const float* __restrict__ bias, float* __restrict__ out) {
    extern __shared__ char sm[];
    float* smf = (float*)sm;
    uint32_t sb = (uint32_t)__cvta_generic_to_shared(sm);

    int seg = blockIdx.z;
    int o0 = blockIdx.x * 128;
    int b0 = blockIdx.y * 128;
    int t = threadIdx.x;
    int warp = t >> 5, lane = t & 31;
    int g = lane >> 2, tg = lane & 3;
    int mW = (warp >> 1) * 64, nW = (warp & 1) * 64;

    const float* Gseg  = g_Gr + (size_t)seg * SEG_FLOATS;
    const float* xTseg = g_xT + (size_t)seg * 512 * 4096 + b0;

    // cp.async addressing (constant per thread)
    // stage s: r = s>>7, xc = s&127 ; B tile = G rows [o0,o0+128), k cols [xc*32, +32)
    auto issue = [&](int s) {
        int buf = s & (STAGES - 1);
        int r = s >> 7, xc = s & 127;
        const float* Gr = Gseg + (size_t)r * CORE_RSTRIDE + (size_t)o0 * 4096 + xc * 32;
        uint32_t bst = sb + buf * BS_STAGE;
#pragma unroll
        for (int j = 0; j < 8; j++) {
            int idx = j * 128 + t;
            int row = idx >> 3, col = idx & 7;
            cpa16(bst + row * BS_ROW + col * 16, Gr + (size_t)row * 4096 + col * 4);
        }
        {
            int xl = t >> 5, sg = t & 31;
            cpa16(sb + XCH_BASE + buf * XCH_STAGE + xl * XCH_ROW + sg * 16,
                  xTseg + (size_t)(xc * 4 + xl) * 4096 + sg * 4);
        }
    };

    float acc[4][8][4];
#pragma unroll
    for (int a = 0; a < 4; a++)
#pragma unroll
        for (int b = 0; b < 8; b++)
#pragma unroll
            for (int c = 0; c < 4; c++) acc[a][b][c] = 0.f;

    int b_of[8];
#pragma unroll
    for (int j = 0; j < 8; j++) b_of[j] = mW + g + j * 8;

#pragma unroll
    for (int s = 0; s < STAGES - 1; s++) {
        issue(s);
        asm volatile("cp.async.commit_group;\n" ::: "memory");
    }

    float et[8], et4[8];

    for (int r = 0; r < 8; r++) {
        const float* ep = g_env + (size_t)(seg * NB + b0) * 64 + r * 8;
#pragma unroll
        for (int j = 0; j < 8; j++) {
            et[j]  = ep[(size_t)b_of[j] * 64 + tg];
            et4[j] = ep[(size_t)b_of[j] * 64 + tg + 4];
        }
        for (int xc = 0; xc < 128; xc++) {
            int s = r * 128 + xc;
            int nxt = s + STAGES - 1;
            if (nxt < 1024) issue(nxt);
            asm volatile("cp.async.commit_group;\n" ::: "memory");
            asm volatile("cp.async.wait_group %0;\n" :: "n"(STAGES - 1) : "memory");
            __syncthreads();
            int buf = s & (STAGES - 1);
            const float* xbuf = smf + (XCH_BASE + buf * XCH_STAGE) / 4;
            const uint32_t* bbuf = (const uint32_t*)(sm + buf * BS_STAGE);

#pragma unroll
            for (int ks = 0; ks < 4; ks++) {
                // x values for the 8 m-rows this thread touches
                const float* xr = xbuf + ks * (XCH_ROW / 4);
                float xv[8];
#pragma unroll
                for (int j = 0; j < 8; j++) xv[j] = xr[b_of[j]];

                // A fragments (pre-rounded tf32)
                uint32_t a[4][4];
#pragma unroll
                for (int mf = 0; mf < 4; mf++) {
                    a[mf][0] = f2tf32(xv[2 * mf + 0] * et[2 * mf + 0]);
                    a[mf][1] = f2tf32(xv[2 * mf + 1] * et[2 * mf + 1]);
                    a[mf][2] = f2tf32(xv[2 * mf + 0] * et4[2 * mf + 0]);
                    a[mf][3] = f2tf32(xv[2 * mf + 1] * et4[2 * mf + 1]);
                }
#pragma unroll
                for (int nf = 0; nf < 8; nf++) {
                    int brow = nW + nf * 8 + g;
                    uint32_t bb[2];
                    bb[0] = bbuf[brow * (BS_ROW / 4) + ks * 8 + tg];      // raw tf32 bits
                    bb[1] = bbuf[brow * (BS_ROW / 4) + ks * 8 + tg + 4];
#pragma unroll
                    for (int mf = 0; mf < 4; mf++)
                        mma_tf32(acc[mf][nf], a[mf], bb);
                }
            }
            __syncthreads();
        }
    }

    // epilogue
    int row0 = b0 + mW + g;
    int cbase = seg * 512 + o0 + nW;
#pragma unroll
    for (int mf = 0; mf < 4; mf++) {
#pragma unroll
        for (int nf = 0; nf < 8; nf++) {
            int col = cbase + nf * 8 + tg * 2;
            float2 bv = *(const float2*)&bias[col];
            int ra = row0 + mf * 16;
            float2 v0 = {acc[mf][nf][0] + bv.x, acc[mf][nf][1] + bv.y};
            float2 v1 = {acc[mf][nf][2] + bv.x, acc[mf][nf][3] + bv.y};
            *(float2*)&out[(size_t)ra * 2048 + col]       = v0;
            *(float2*)&out[(size_t)(ra + 8) * 2048 + col] = v1;
        }
    }
}

// ================= launch =================
extern "C" void kernel_launch(void* const* d_in, const int* in_sizes, int n_in,
                              void* d_out, int out_size) {
    (void)in_sizes; (void)n_in; (void)out_size;
    const float* x    = (const float*)d_in[0];
    const float* c0   = (const float*)d_in[1];
    const float* c1   = (const float*)d_in[2];
    const float* c2   = (const float*)d_in[3];
    const float* c3   = (const float*)d_in[4];
    const float* bias = (const float*)d_in[5];
    float* out = (float*)d_out;

    cudaFuncSetAttribute(k_gemm, cudaFuncAttributeMaxDynamicSharedMemorySize, GEMM_SMEM);

    k_round<<<dim3(2048, 4), 256>>>(c0, c1, c2, c3);
    k_transpose<<<dim3(64, 128), dim3(32, 8)>>>(x);
    k_gsum<<<dim3(128, 4), 256>>>(c0, c1, c2, c3);
    k_S<<<dim3(256, 4), 256>>>(x);
    k_env<<<4096, 64>>>();
    k_gemm<<<dim3(4, 32, 4), 128, GEMM_SMEM>>>(bias, out);
}

// round 13
// speedup vs baseline: 2.0859x; 1.8934x over previous
#include <cuda_runtime.h>
#include <cuda_fp16.h>
#include <cstdint>
#include <cstddef>

// ---------------- problem constants ----------------
#define NB 4096
#define CORE_RSTRIDE 2097152   // 512*512*8 elements (r stride)
#define SEG_FLOATS   16777216  // 8 * CORE_RSTRIDE

// ---------------- scratch (device globals) ----------------
__device__ __half g_Gh[4ull * SEG_FLOATS];   // fp16 copy of G (128 MB)
__device__ float g_xT[2048 * 4096];          // xT[d][b]  (32 MB)
__device__ float g_Gsum[4 * 8 * 4096];
__device__ float g_S[4 * NB * 64];
__device__ float g_env[4 * NB * 64];

// ---------------- helpers ----------------
__device__ __forceinline__ uint32_t h2pack(float hi, float lo) {
    uint32_t d;
    asm("cvt.rn.f16x2.f32 %0, %1, %2;\n" : "=r"(d) : "f"(hi), "f"(lo));
    return d;
}
__device__ __forceinline__ void cpa16(uint32_t saddr, const void* g) {
    asm volatile("cp.async.cg.shared.global [%0], [%1], 16;\n" :: "r"(saddr), "l"(g) : "memory");
}
__device__ __forceinline__ void mma_f16(float* c, const uint32_t* a, const uint32_t* b) {
    asm volatile(
        "mma.sync.aligned.m16n8k16.row.col.f32.f16.f16.f32 "
        "{%0,%1,%2,%3}, {%4,%5,%6,%7}, {%8,%9}, {%0,%1,%2,%3};\n"
        : "+f"(c[0]), "+f"(c[1]), "+f"(c[2]), "+f"(c[3])
        : "r"(a[0]), "r"(a[1]), "r"(a[2]), "r"(a[3]), "r"(b[0]), "r"(b[1]));
}

// ================= kernel 0: convert G -> fp16 =================
__global__ void k_half(const float* __restrict__ c0, const float* __restrict__ c1,
                       const float* __restrict__ c2, const float* __restrict__ c3) {
    int seg = blockIdx.y;
    const float* G = (seg == 0) ? c0 : (seg == 1) ? c1 : (seg == 2) ? c2 : c3;
    const float4* src = (const float4*)G;
    uint2* dst = (uint2*)(g_Gh + (size_t)seg * SEG_FLOATS);
    size_t base = (size_t)blockIdx.x * 2048 + threadIdx.x;
#pragma unroll
    for (int j = 0; j < 8; j++) {
        size_t k = base + (size_t)j * 256;
        float4 v = src[k];
        uint2 o;
        o.x = h2pack(v.y, v.x);
        o.y = h2pack(v.w, v.z);
        dst[k] = o;
    }
}

// ================= kernel 1: transpose x =================
__global__ void k_transpose(const float* __restrict__ x) {
    __shared__ float tile[32][33];
    int d0 = blockIdx.x * 32, b0 = blockIdx.y * 32;
    int tx = threadIdx.x, ty = threadIdx.y;
#pragma unroll
    for (int j = 0; j < 32; j += 8)
        tile[ty + j][tx] = x[(size_t)(b0 + ty + j) * 2048 + d0 + tx];
    __syncthreads();
#pragma unroll
    for (int j = 0; j < 32; j += 8)
        g_xT[(size_t)(d0 + ty + j) * 4096 + b0 + tx] = tile[tx][ty + j];
}

// ================= kernel 2: Gsum =================
__global__ void k_gsum(const float* __restrict__ c0, const float* __restrict__ c1,
                       const float* __restrict__ c2, const float* __restrict__ c3) {
    int i = blockIdx.y;
    const float* G = (i == 0) ? c0 : (i == 1) ? c1 : (i == 2) ? c2 : c3;
    int idx = blockIdx.x * 256 + threadIdx.x;
    int r = idx >> 12, xs = idx & 4095;
    const float* p = G + (size_t)r * CORE_RSTRIDE + xs;
    float s = 0.f;
#pragma unroll 8
    for (int o = 0; o < 512; o++) s += p[(size_t)o * 4096];
    g_Gsum[(size_t)(i * 8 + r) * 4096 + xs] = s;
}

// ================= kernel 3: S =================
__global__ void k_S(const float* __restrict__ x) {
    __shared__ float xs_[512][17];
    int i = blockIdx.y;
    int b0 = blockIdx.x * 16;
    int t = threadIdx.x;
    for (int idx = t; idx < 16 * 512; idx += 256) {
        int b = idx >> 9, xc = idx & 511;
        xs_[xc][b] = x[(size_t)(b0 + b) * 2048 + i * 512 + xc];
    }
    __syncthreads();
    int rs = t & 63, bq = t >> 6;
    int s = rs & 7, r = rs >> 3;
    const float* gp = g_Gsum + (size_t)(i * 8 + r) * 4096 + s;
    float acc[4] = {0.f, 0.f, 0.f, 0.f};
    for (int xc = 0; xc < 512; xc++) {
        float gv = gp[xc * 8];
#pragma unroll
        for (int j = 0; j < 4; j++) acc[j] += gv * xs_[xc][bq + j * 4];
    }
#pragma unroll
    for (int j = 0; j < 4; j++)
        g_S[(size_t)(i * NB + b0 + bq + j * 4) * 64 + rs] = acc[j];
}

// ================= kernel 4: ring products -> env =================
__global__ void k_env() {
    int b = blockIdx.x, t = threadIdx.x;
    int r = t >> 3, c = t & 7;
    __shared__ float Sm[4][64], P2[64], P3[64], Q1[64], Q0[64], E[64];
#pragma unroll
    for (int i = 0; i < 4; i++) Sm[i][t] = g_S[(size_t)(i * NB + b) * 64 + t];
    __syncthreads();
    float v;
    v = 0.f;
#pragma unroll
    for (int k = 0; k < 8; k++) v += Sm[0][r * 8 + k] * Sm[1][k * 8 + c];
    P2[t] = v;
    v = 0.f;
#pragma unroll
    for (int k = 0; k < 8; k++) v += Sm[2][r * 8 + k] * Sm[3][k * 8 + c];
    Q1[t] = v;
    __syncthreads();
    v = 0.f;
#pragma unroll
    for (int k = 0; k < 8; k++) v += P2[r * 8 + k] * Sm[2][k * 8 + c];
    P3[t] = v;
    v = 0.f;
#pragma unroll
    for (int k = 0; k < 8; k++) v += Sm[1][r * 8 + k] * Q1[k * 8 + c];
    Q0[t] = v;
    __syncthreads();
    g_env[(size_t)(0 * NB + b) * 64 + t] = Q0[c * 8 + r];
    g_env[(size_t)(3 * NB + b) * 64 + t] = P3[c * 8 + r];
    v = 0.f;
#pragma unroll
    for (int k = 0; k < 8; k++) v += Q1[r * 8 + k] * Sm[0][k * 8 + c];
    E[t] = v;
    __syncthreads();
    g_env[(size_t)(1 * NB + b) * 64 + t] = E[c * 8 + r];
    __syncthreads();
    v = 0.f;
#pragma unroll
    for (int k = 0; k < 8; k++) v += Sm[3][r * 8 + k] * P2[k * 8 + c];
    E[t] = v;
    __syncthreads();
    g_env[(size_t)(2 * NB + b) * 64 + t] = E[c * 8 + r];
}

// ================= kernel 5: main GEMM (fp16 m16n8k16) =================
// CTA 128(M=b) x 128(N=o), 128 threads (2x2 warps, warp tile 64x64).
// out[b, seg*512+o] = sum_r sum_k A_r[b,k]*G[r][o,k] + bias, k=x*8+s.
// A_r[b,k] = x[b]*env[b,r,s] built in regs, packed fp16 via cvt.rn.f16x2.
// B = fp16 G from g_Gh (raw bits -> mma).
// Stage: K=64 (8 x-values, 4 k16 chunks). 512 stages total.
#define STAGES 4
// smem layout (bytes):
//   Bs:  [4][128 rows][72 halfs] -> stage 18432, row 144 (36 words: banks 4g+tg, conflict-free)
//   xch: [4][8][132 f32]         -> base 73728, stage 4224, row 528
#define BS_STAGE   18432
#define BS_ROW_W   36          // words per B row
#define XCH_BASE   73728
#define XCH_STAGE  4224
#define XCH_ROW_F  132
#define GEMM_SMEM  (XCH_BASE + STAGES * XCH_STAGE)

__global__ void __launch_bounds__(128, 2) k_gemm(
    const float* __restrict__ bias, float* __restrict__ out) {
    extern __shared__ char sm[];
    float* smf = (float*)sm;
    uint32_t* smw = (uint32_t*)sm;
    uint32_t sb = (uint32_t)__cvta_generic_to_shared(sm);

    int seg = blockIdx.z;
    int o0 = blockIdx.x * 128;
    int b0 = blockIdx.y * 128;
    int t = threadIdx.x;
    int warp = t >> 5, lane = t & 31;
    int g = lane >> 2, tg = lane & 3;
    int mW = (warp >> 1) * 64, nW = (warp & 1) * 64;

    const __half* Ghseg = g_Gh + (size_t)seg * SEG_FLOATS;
    const float*  xTseg = g_xT + (size_t)seg * 512 * 4096 + b0;

    // stage s (0..511): r = s>>6, stx = s&63 ; k-window = [stx*64, +64)
    auto issue = [&](int s) {
        int buf = s & (STAGES - 1);
        int r = s >> 6, stx = s & 63;
        const __half* Gr = Ghseg + (size_t)r * CORE_RSTRIDE + (size_t)o0 * 4096 + stx * 64;
        uint32_t bst = sb + buf * BS_STAGE;
#pragma unroll
        for (int j = 0; j < 8; j++) {          // 128 rows x 8 chunks of 16B
            int idx = j * 128 + t;
            int row = idx >> 3, col = idx & 7;
            cpa16(bst + row * 144 + col * 16, Gr + (size_t)row * 4096 + col * 8);
        }
#pragma unroll
        for (int j = 0; j < 2; j++) {          // 8 x-rows x 32 chunks of 16B
            int idx = j * 128 + t;
            int xl = idx >> 5, c = idx & 31;
            cpa16(sb + XCH_BASE + buf * XCH_STAGE + xl * 528 + c * 16,
                  xTseg + (size_t)(stx * 8 + xl) * 4096 + c * 4);
        }
    };

    float acc[4][8][4];
#pragma unroll
    for (int a = 0; a < 4; a++)
#pragma unroll
        for (int b = 0; b < 8; b++)
#pragma unroll
            for (int c = 0; c < 4; c++) acc[a][b][c] = 0.f;

    int b_of[8];
#pragma unroll
    for (int j = 0; j < 8; j++) b_of[j] = mW + g + j * 8;

#pragma unroll
    for (int s = 0; s < STAGES - 1; s++) {
        issue(s);
        asm volatile("cp.async.commit_group;\n" ::: "memory");
    }

    float e0[8], e1[8];

    for (int s = 0; s < 512; s++) {
        if ((s & 63) == 0) {
            int r = s >> 6;
            const float* ep = g_env + (size_t)(seg * NB + b0) * 64 + r * 8 + 2 * tg;
#pragma unroll
            for (int j = 0; j < 8; j++) {
                float2 e = *(const float2*)(ep + (size_t)b_of[j] * 64);
                e0[j] = e.x; e1[j] = e.y;
            }
        }
        // stage s data arrived when <=2 newer groups outstanding
        asm volatile("cp.async.wait_group 2;\n" ::: "memory");
        __syncthreads();    // everyone done reading buf (s-1)&3 and sees stage s
        int nxt = s + STAGES - 1;
        if (nxt < 512) issue(nxt);
        asm volatile("cp.async.commit_group;\n" ::: "memory");

        int buf = s & (STAGES - 1);
        const float* xbuf = smf + (XCH_BASE + buf * XCH_STAGE) / 4;
        const uint32_t* bbuf = smw + (buf * BS_STAGE) / 4;

#pragma unroll
        for (int ch = 0; ch < 4; ch++) {       // k16 chunks: x-locals 2ch, 2ch+1
            const float* xr0 = xbuf + (2 * ch) * XCH_ROW_F;
            const float* xr1 = xbuf + (2 * ch + 1) * XCH_ROW_F;
            float xv0[8], xv1[8];
#pragma unroll
            for (int j = 0; j < 8; j++) { xv0[j] = xr0[b_of[j]]; xv1[j] = xr1[b_of[j]]; }

            uint32_t a[4][4];
#pragma unroll
            for (int mf = 0; mf < 4; mf++) {
                int jl = 2 * mf, jh = 2 * mf + 1;
                a[mf][0] = h2pack(xv0[jl] * e1[jl], xv0[jl] * e0[jl]);
                a[mf][1] = h2pack(xv0[jh] * e1[jh], xv0[jh] * e0[jh]);
                a[mf][2] = h2pack(xv1[jl] * e1[jl], xv1[jl] * e0[jl]);
                a[mf][3] = h2pack(xv1[jh] * e1[jh], xv1[jh] * e0[jh]);
            }
#pragma unroll
            for (int nf = 0; nf < 8; nf++) {
                int row = nW + nf * 8 + g;
                uint32_t bb[2];
                bb[0] = bbuf[row * BS_ROW_W + ch * 8 + tg];
                bb[1] = bbuf[row * BS_ROW_W + ch * 8 + tg + 4];
#pragma unroll
                for (int mf = 0; mf < 4; mf++)
                    mma_f16(acc[mf][nf], a[mf], bb);
            }
        }
    }
    __syncthreads();

    // epilogue
    int row0 = b0 + mW + g;
    int cbase = seg * 512 + o0 + nW;
#pragma unroll
    for (int mf = 0; mf < 4; mf++) {
#pragma unroll
        for (int nf = 0; nf < 8; nf++) {
            int col = cbase + nf * 8 + tg * 2;
            float2 bv = *(const float2*)&bias[col];
            int ra = row0 + mf * 16;
            float2 v0 = {acc[mf][nf][0] + bv.x, acc[mf][nf][1] + bv.y};
            float2 v1 = {acc[mf][nf][2] + bv.x, acc[mf][nf][3] + bv.y};
            *(float2*)&out[(size_t)ra * 2048 + col]       = v0;
            *(float2*)&out[(size_t)(ra + 8) * 2048 + col] = v1;
        }
    }
}

// ================= launch =================
extern "C" void kernel_launch(void* const* d_in, const int* in_sizes, int n_in,
                              void* d_out, int out_size) {
    (void)in_sizes; (void)n_in; (void)out_size;
    const float* x    = (const float*)d_in[0];
    const float* c0   = (const float*)d_in[1];
    const float* c1   = (const float*)d_in[2];
    const float* c2   = (const float*)d_in[3];
    const float* c3   = (const float*)d_in[4];
    const float* bias = (const float*)d_in[5];
    float* out = (float*)d_out;

    cudaFuncSetAttribute(k_gemm, cudaFuncAttributeMaxDynamicSharedMemorySize, GEMM_SMEM);

    k_half<<<dim3(2048, 4), 256>>>(c0, c1, c2, c3);
    k_transpose<<<dim3(64, 128), dim3(32, 8)>>>(x);
    k_gsum<<<dim3(128, 4), 256>>>(c0, c1, c2, c3);
    k_S<<<dim3(256, 4), 256>>>(x);
    k_env<<<4096, 64>>>();
    k_gemm<<<dim3(4, 32, 4), 128, GEMM_SMEM>>>(bias, out);
}